// round 12
// baseline (speedup 1.0000x reference)
#include <cuda_runtime.h>
#include <cuda_fp16.h>
#include <cstdint>

// NetVladCNN: B=64, D=512, H=W=32 (N=1024), K=64
// x: (B,D,H,W) fp32   w: (K,D)   c: (K,D)   out: (D,K,B) fp32
//
// Stage 1 (fp16 mma, pipelined): features = w·x -> g_a16 (fp16)
// Stage 2: softmax over h on fp16 (fp32 math)
// Stage 3 (fp16 mma, pipelined): C[d,k] = sum_n x[d,n]*a[k,n]; V = C - 32*c^T;
//         warp-local k-normalize; g_v[b][d][k] fp32
// Stage 4: transpose g_v [b][dk] -> out [dk][b]

#define BB 64
#define DD 512
#define NN 1024
#define KK 64
#define EPSN 1e-12f

__device__ uint32_t g_a16u[(size_t)BB * KK * (NN / 2)];  // fp16x2 features / a
__device__ float g_v[(size_t)BB * DD * KK];              // normalized V [b][d][k]

// ---------- fp16 mma helpers ----------
__device__ __forceinline__ void mma16(float* c, const uint32_t* a, uint32_t b0,
                                      uint32_t b1) {
    asm volatile(
        "mma.sync.aligned.m16n8k16.row.col.f32.f16.f16.f32 "
        "{%0,%1,%2,%3}, {%4,%5,%6,%7}, {%8,%9}, {%0,%1,%2,%3};"
        : "+f"(c[0]), "+f"(c[1]), "+f"(c[2]), "+f"(c[3])
        : "r"(a[0]), "r"(a[1]), "r"(a[2]), "r"(a[3]), "r"(b0), "r"(b1));
}
__device__ __forceinline__ uint32_t packh(float e, float o) {
    uint32_t r;
    asm("cvt.rn.f16x2.f32 %0, %1, %2;" : "=r"(r) : "f"(o), "f"(e));
    return r;
}

// ============================================================================
// Kernel 1: features GEMM, pipelined. CTA: 64k x 128n per b, chunks d=32.
// 8 warps: warp tile m32(k) x n32 (2 mi x 4 j).
// ============================================================================
#define SWP 20    // sW row stride (u32)
#define SXP 136   // sX row stride (u32), ≡8 mod 32
__global__ __launch_bounds__(256, 2) void k_feat(const float* __restrict__ x,
                                                 const float* __restrict__ wt) {
    __shared__ uint32_t sW[64][SWP];   // [k][d-pair 16] f16x2
    __shared__ uint32_t sX[16][SXP];   // [d-pair][n 128] f16x2

    const int b = blockIdx.y, n0 = blockIdx.x * 128;
    const int t = threadIdx.x, lane = t & 31, warp = t >> 5;
    const int g = lane >> 2, tq = lane & 3;
    const int k0 = (warp >> 2) * 32;
    const int nb = (warp & 3) * 32;
    const float* xb = x + (size_t)b * DD * NN;

    float acc[2][4][4];
#pragma unroll
    for (int i = 0; i < 2; i++)
#pragma unroll
        for (int j = 0; j < 4; j++)
#pragma unroll
            for (int r = 0; r < 4; r++) acc[i][j][r] = 0.f;

    const int wrow = t & 63, wseg = t >> 6;   // w: 64 rows x 4 segs x 8 d
    const int xdp = t >> 4, xtx = t & 15;     // x: 16 d-pairs x 16 col-groups x 8

    float4 rw0, rw1, rxe0, rxe1, rxo0, rxo1;

#define FEAT_LOAD(D0)                                                          \
    {                                                                          \
        const float* ws = wt + (size_t)wrow * DD + (D0) + wseg * 8;            \
        rw0 = *(const float4*)ws;                                              \
        rw1 = *(const float4*)(ws + 4);                                        \
        const float* se = xb + (size_t)((D0) + 2 * xdp) * NN + n0 + xtx * 8;   \
        const float* so = se + NN;                                             \
        rxe0 = *(const float4*)se;                                             \
        rxe1 = *(const float4*)(se + 4);                                       \
        rxo0 = *(const float4*)so;                                             \
        rxo1 = *(const float4*)(so + 4);                                       \
    }

#define FEAT_STORE()                                                           \
    {                                                                          \
        sW[wrow][wseg * 4 + 0] = packh(rw0.x, rw0.y);                          \
        sW[wrow][wseg * 4 + 1] = packh(rw0.z, rw0.w);                          \
        sW[wrow][wseg * 4 + 2] = packh(rw1.x, rw1.y);                          \
        sW[wrow][wseg * 4 + 3] = packh(rw1.z, rw1.w);                          \
        *(uint4*)&sX[xdp][xtx * 8] =                                           \
            make_uint4(packh(rxe0.x, rxo0.x), packh(rxe0.y, rxo0.y),           \
                       packh(rxe0.z, rxo0.z), packh(rxe0.w, rxo0.w));          \
        *(uint4*)&sX[xdp][xtx * 8 + 4] =                                       \
            make_uint4(packh(rxe1.x, rxo1.x), packh(rxe1.y, rxo1.y),           \
                       packh(rxe1.z, rxo1.z), packh(rxe1.w, rxo1.w));          \
    }

    FEAT_LOAD(0);
    FEAT_STORE();
    __syncthreads();

    for (int c = 0; c < 16; c++) {
        if (c + 1 < 16) FEAT_LOAD((c + 1) * 32);

#pragma unroll
        for (int s = 0; s < 2; s++) {
            const int sp = s * 8;
            uint32_t a[2][4];
#pragma unroll
            for (int mi = 0; mi < 2; mi++) {
                const int r0 = k0 + mi * 16 + g;
                a[mi][0] = sW[r0][sp + tq];
                a[mi][1] = sW[r0 + 8][sp + tq];
                a[mi][2] = sW[r0][sp + tq + 4];
                a[mi][3] = sW[r0 + 8][sp + tq + 4];
            }
#pragma unroll
            for (int j = 0; j < 4; j++) {
                const int n = nb + j * 8 + g;
                uint32_t b0 = sX[sp + tq][n];
                uint32_t b1 = sX[sp + tq + 4][n];
                mma16(acc[0][j], a[0], b0, b1);
                mma16(acc[1][j], a[1], b0, b1);
            }
        }
        __syncthreads();
        if (c + 1 < 16) {
            FEAT_STORE();
            __syncthreads();
        }
    }

    // epilogue: write fp16 pairs (n even/odd) to g_a16u
#pragma unroll
    for (int mi = 0; mi < 2; mi++) {
#pragma unroll
        for (int j = 0; j < 4; j++) {
            const int k = k0 + mi * 16 + g;
            const int np = (n0 + nb + j * 8 + 2 * tq) >> 1;
            g_a16u[((size_t)b * KK + k) * (NN / 2) + np] =
                packh(acc[mi][j][0], acc[mi][j][1]);
            g_a16u[((size_t)b * KK + k + 8) * (NN / 2) + np] =
                packh(acc[mi][j][2], acc[mi][j][3]);
        }
    }
}

// ============================================================================
// Kernel 2: softmax over h on fp16 pairs. One block per (b,k) row.
// u32 index i = h*16 + wp (wp = w/2, two independent w columns per u32).
// ============================================================================
__global__ __launch_bounds__(256) void k_softmax() {
    __shared__ float2 red[16][17];
    uint32_t* p = g_a16u + (size_t)blockIdx.x * (NN / 2);
    const int t = threadIdx.x;
    const int j = t >> 4, wp = t & 15;

    uint32_t u0 = p[t], u1 = p[t + 256];   // h = j, h = j+16
    float2 f0 = __half22float2(*(__half2*)&u0);
    float2 f1 = __half22float2(*(__half2*)&u1);

    red[j][wp] = make_float2(fmaxf(f0.x, f1.x), fmaxf(f0.y, f1.y));
    __syncthreads();
    float2 mm = red[0][wp];
#pragma unroll
    for (int q = 1; q < 16; q++) {
        float2 r = red[q][wp];
        mm.x = fmaxf(mm.x, r.x);
        mm.y = fmaxf(mm.y, r.y);
    }
    __syncthreads();

    float e0x = __expf(f0.x - mm.x), e0y = __expf(f0.y - mm.y);
    float e1x = __expf(f1.x - mm.x), e1y = __expf(f1.y - mm.y);
    red[j][wp] = make_float2(e0x + e1x, e0y + e1y);
    __syncthreads();
    float2 ss = make_float2(0.f, 0.f);
#pragma unroll
    for (int q = 0; q < 16; q++) {
        float2 r = red[q][wp];
        ss.x += r.x;
        ss.y += r.y;
    }
    float ix = 1.0f / ss.x, iy = 1.0f / ss.y;

    p[t] = packh(e0x * ix, e0y * iy);
    p[t + 256] = packh(e1x * ix, e1y * iy);
}

// ============================================================================
// Kernel 3: V GEMM, pipelined. CTA: 128d x 64k per b, chunks n=32.
// sA is a pure u32 copy from fp16 a. Epilogue: V=C-32c, warp-local norm.
// ============================================================================
#define VP 20
__global__ __launch_bounds__(256, 2) void k_vlad(const float* __restrict__ x,
                                                 const float* __restrict__ cc) {
    __shared__ uint32_t sA[64][VP];    // [k][n-pair 16] f16x2
    __shared__ uint32_t sX[128][VP];   // [d][n-pair 16] f16x2

    const int b = blockIdx.y, d0 = blockIdx.x * 128;
    const int t = threadIdx.x, lane = t & 31, warp = t >> 5;
    const int g = lane >> 2, tq = lane & 3;
    const int m0 = warp * 16;
    const float* xb = x + (size_t)b * DD * NN;
    const uint32_t* ab = g_a16u + (size_t)b * KK * (NN / 2);

    float acc[8][4];
#pragma unroll
    for (int j = 0; j < 8; j++)
#pragma unroll
        for (int r = 0; r < 4; r++) acc[j][r] = 0.f;

    const int arow = t & 63, aseg = t >> 6;   // a: 64 rows x 4 uint4
    const int xrow = t >> 1, xseg = t & 1;    // x: 128 rows x 2 halves x 16 f

    uint4 ra;
    float4 rx0, rx1, rx2, rx3;

#define VLAD_LOAD(N0)                                                          \
    {                                                                          \
        ra = *(const uint4*)(ab + (size_t)arow * (NN / 2) + (N0) / 2 + aseg * 4); \
        const float* src = xb + (size_t)(d0 + xrow) * NN + (N0) + xseg * 16;   \
        rx0 = *(const float4*)src;                                             \
        rx1 = *(const float4*)(src + 4);                                       \
        rx2 = *(const float4*)(src + 8);                                       \
        rx3 = *(const float4*)(src + 12);                                      \
    }

#define VLAD_STORE()                                                           \
    {                                                                          \
        *(uint4*)&sA[arow][aseg * 4] = ra;                                     \
        *(uint4*)&sX[xrow][xseg * 8] =                                         \
            make_uint4(packh(rx0.x, rx0.y), packh(rx0.z, rx0.w),               \
                       packh(rx1.x, rx1.y), packh(rx1.z, rx1.w));              \
        *(uint4*)&sX[xrow][xseg * 8 + 4] =                                     \
            make_uint4(packh(rx2.x, rx2.y), packh(rx2.z, rx2.w),               \
                       packh(rx3.x, rx3.y), packh(rx3.z, rx3.w));              \
    }

    VLAD_LOAD(0);
    VLAD_STORE();
    __syncthreads();

    for (int c = 0; c < 32; c++) {
        if (c + 1 < 32) VLAD_LOAD((c + 1) * 32);

#pragma unroll
        for (int s = 0; s < 2; s++) {
            const int sp = s * 8;
            uint32_t a[4];
            a[0] = sX[m0 + g][sp + tq];
            a[1] = sX[m0 + g + 8][sp + tq];
            a[2] = sX[m0 + g][sp + tq + 4];
            a[3] = sX[m0 + g + 8][sp + tq + 4];
#pragma unroll
            for (int j = 0; j < 8; j++) {
                const int kc = j * 8 + g;
                uint32_t b0 = sA[kc][sp + tq];
                uint32_t b1 = sA[kc][sp + tq + 4];
                mma16(acc[j], a, b0, b1);
            }
        }
        __syncthreads();
        if (c + 1 < 32) {
            VLAD_STORE();
            __syncthreads();
        }
    }

    // epilogue: rows d = d0+m0+g (+8); cols k = j*8+2tq(+1)
#pragma unroll
    for (int half = 0; half < 2; half++) {
        const int d = d0 + m0 + g + half * 8;
        float v[16];
        float s = 0.f;
#pragma unroll
        for (int j = 0; j < 8; j++) {
            const int k = j * 8 + 2 * tq;
            float c0 = cc[(size_t)k * DD + d];
            float c1 = cc[(size_t)(k + 1) * DD + d];
            float v0 = acc[j][half * 2 + 0] - 32.f * c0;
            float v1 = acc[j][half * 2 + 1] - 32.f * c1;
            v[j * 2] = v0; v[j * 2 + 1] = v1;
            s += v0 * v0 + v1 * v1;
        }
        s += __shfl_xor_sync(0xffffffffu, s, 1);
        s += __shfl_xor_sync(0xffffffffu, s, 2);
        float n1 = fmaxf(sqrtf(s), EPSN);
        float n2 = fmaxf(sqrtf(s) / n1, EPSN);
        float inv = 1.0f / (n1 * n2);
        float* dst = g_v + ((size_t)b * DD + d) * KK;
#pragma unroll
        for (int j = 0; j < 8; j++)
            *(float2*)(dst + j * 8 + 2 * tq) =
                make_float2(v[j * 2] * inv, v[j * 2 + 1] * inv);
    }
}

// ============================================================================
// Kernel 4: transpose g_v [b][dk] -> out [dk][b]
// ============================================================================
__global__ __launch_bounds__(256) void k_tr(float* __restrict__ out) {
    __shared__ float tile[32][33];
    const int bx = blockIdx.x * 32;   // dk
    const int by = blockIdx.y * 32;   // b
    const int tx = threadIdx.x & 31;
    const int ty = threadIdx.x >> 5;

#pragma unroll
    for (int i = 0; i < 32; i += 8)
        tile[ty + i][tx] = g_v[(size_t)(by + ty + i) * (DD * KK) + bx + tx];
    __syncthreads();
#pragma unroll
    for (int i = 0; i < 32; i += 8)
        out[(size_t)(bx + ty + i) * BB + by + tx] = tile[tx][ty + i];
}

// ============================================================================
extern "C" void kernel_launch(void* const* d_in, const int* in_sizes, int n_in,
                              void* d_out, int out_size) {
    const float* x  = (const float*)d_in[0];
    const float* wt = (const float*)d_in[1];
    const float* c  = (const float*)d_in[2];
    float* out = (float*)d_out;

    k_feat<<<dim3(NN / 128, BB), 256>>>(x, wt);

    k_softmax<<<BB * KK, 256>>>();

    k_vlad<<<dim3(DD / 128, BB), 256>>>(x, c);

    k_tr<<<dim3(DD * KK / 32, BB / 32), 256>>>(out);
}

// round 14
// speedup vs baseline: 1.0932x; 1.0932x over previous
#include <cuda_runtime.h>
#include <cuda_fp16.h>
#include <cstdint>

// NetVladCNN: B=64, D=512, H=W=32 (N=1024), K=64
// x: (B,D,H,W) fp32   w: (K,D)   c: (K,D)   out: (D,K,B) fp32
//
// Stage 1 (fp16 mma): features = w·x -> g_a16u (fp16x2)
// Stage 2: softmax over h on fp16 pairs (fp32 math)
// Stage 3 (fp16 mma): C[d,k] = sum_n x[d,n]*a[k,n]; V = C - 32*c^T;
//         warp-local k-normalize; g_v[b][d][k] fp32
// Stage 4: transpose g_v [b][dk] -> out [dk][b]

#define BB 64
#define DD 512
#define NN 1024
#define KK 64
#define EPSN 1e-12f

__device__ uint32_t g_a16u[(size_t)BB * KK * (NN / 2)];  // fp16x2 features / a
__device__ float g_v[(size_t)BB * DD * KK];              // normalized V

// ---------- fp16 mma helpers ----------
__device__ __forceinline__ void mma16(float* c, const uint32_t* a, uint32_t b0,
                                      uint32_t b1) {
    asm volatile(
        "mma.sync.aligned.m16n8k16.row.col.f32.f16.f16.f32 "
        "{%0,%1,%2,%3}, {%4,%5,%6,%7}, {%8,%9}, {%0,%1,%2,%3};"
        : "+f"(c[0]), "+f"(c[1]), "+f"(c[2]), "+f"(c[3])
        : "r"(a[0]), "r"(a[1]), "r"(a[2]), "r"(a[3]), "r"(b0), "r"(b1));
}
__device__ __forceinline__ uint32_t packh(float e, float o) {
    uint32_t r;
    asm("cvt.rn.f16x2.f32 %0, %1, %2;" : "=r"(r) : "f"(o), "f"(e));
    return r;
}

// ============================================================================
// Kernel 1: features GEMM (fp16 mma), R11 structure.
// Per b: M=64 (k), N'=256 (n tile), contraction d=512 in chunks of 32.
// 256 thr = 8 warps; warp tile = m32 x n64 (2 m-tiles x 8 n-frags).
// ============================================================================
#define WPAD 20
#define XPAD 264
__global__ __launch_bounds__(256, 2) void k_feat(const float* __restrict__ x,
                                                 const float* __restrict__ wt) {
    __shared__ uint32_t sW[64][WPAD];   // [k][d-pair 16] f16x2
    __shared__ uint32_t sX[16][XPAD];   // [d-pair][n 256] f16x2

    const int b = blockIdx.y, n0 = blockIdx.x * 256;
    const int t = threadIdx.x, lane = t & 31, warp = t >> 5;
    const int g = lane >> 2, tq = lane & 3;
    const int k0 = (warp >> 2) * 32;
    const int nb = (warp & 3) * 64;
    const float* xb = x + (size_t)b * DD * NN;

    float acc[2][8][4];
#pragma unroll
    for (int i = 0; i < 2; i++)
#pragma unroll
        for (int j = 0; j < 8; j++)
#pragma unroll
            for (int r = 0; r < 4; r++) acc[i][j][r] = 0.f;

    const int wrow = t & 63, wseg = t >> 6;   // w loader
    const int xdp = t >> 4, xtx = t & 15;     // x loader

    for (int d0 = 0; d0 < DD; d0 += 32) {
        {
            const float* src = wt + (size_t)wrow * DD + d0 + wseg * 8;
            float4 v0 = *(const float4*)src;
            float4 v1 = *(const float4*)(src + 4);
            sW[wrow][wseg * 4 + 0] = packh(v0.x, v0.y);
            sW[wrow][wseg * 4 + 1] = packh(v0.z, v0.w);
            sW[wrow][wseg * 4 + 2] = packh(v1.x, v1.y);
            sW[wrow][wseg * 4 + 3] = packh(v1.z, v1.w);
        }
        {
            const float* se = xb + (size_t)(d0 + 2 * xdp) * NN + n0;
            const float* so = se + NN;
#pragma unroll
            for (int q = 0; q < 4; q++) {
                const int col = xtx * 4 + 64 * q;
                float4 ve = *(const float4*)(se + col);
                float4 vo = *(const float4*)(so + col);
                *(uint4*)&sX[xdp][col] =
                    make_uint4(packh(ve.x, vo.x), packh(ve.y, vo.y),
                               packh(ve.z, vo.z), packh(ve.w, vo.w));
            }
        }
        __syncthreads();

#pragma unroll
        for (int s = 0; s < 2; s++) {
            const int sp = s * 8;
            uint32_t a[2][4];
#pragma unroll
            for (int mi = 0; mi < 2; mi++) {
                const int r0 = k0 + mi * 16 + g;
                a[mi][0] = sW[r0][sp + tq];
                a[mi][1] = sW[r0 + 8][sp + tq];
                a[mi][2] = sW[r0][sp + tq + 4];
                a[mi][3] = sW[r0 + 8][sp + tq + 4];
            }
#pragma unroll
            for (int j = 0; j < 8; j++) {
                const int n = nb + j * 8 + g;
                uint32_t b0 = sX[sp + tq][n];
                uint32_t b1 = sX[sp + tq + 4][n];
                mma16(acc[0][j], a[0], b0, b1);
                mma16(acc[1][j], a[1], b0, b1);
            }
        }
        __syncthreads();
    }

    // epilogue: pack fp16 pairs (n, n+1) into g_a16u
#pragma unroll
    for (int mi = 0; mi < 2; mi++) {
#pragma unroll
        for (int j = 0; j < 8; j++) {
            const int k = k0 + mi * 16 + g;
            const int np = (n0 + nb + j * 8 + 2 * tq) >> 1;
            g_a16u[((size_t)b * KK + k) * (NN / 2) + np] =
                packh(acc[mi][j][0], acc[mi][j][1]);
            g_a16u[((size_t)b * KK + k + 8) * (NN / 2) + np] =
                packh(acc[mi][j][2], acc[mi][j][3]);
        }
    }
}

// ============================================================================
// Kernel 2: softmax over h on fp16 pairs. One block per (b,k) row.
// u32 index i = h*16 + wp (wp = w/2; two independent w columns per u32).
// ============================================================================
__global__ __launch_bounds__(256) void k_softmax() {
    __shared__ float2 red[16][17];
    uint32_t* p = g_a16u + (size_t)blockIdx.x * (NN / 2);
    const int t = threadIdx.x;
    const int j = t >> 4, wp = t & 15;

    uint32_t u0 = p[t], u1 = p[t + 256];   // h = j, h = j+16
    float2 f0 = __half22float2(*(__half2*)&u0);
    float2 f1 = __half22float2(*(__half2*)&u1);

    red[j][wp] = make_float2(fmaxf(f0.x, f1.x), fmaxf(f0.y, f1.y));
    __syncthreads();
    float2 mm = red[0][wp];
#pragma unroll
    for (int q = 1; q < 16; q++) {
        float2 r = red[q][wp];
        mm.x = fmaxf(mm.x, r.x);
        mm.y = fmaxf(mm.y, r.y);
    }
    __syncthreads();

    float e0x = __expf(f0.x - mm.x), e0y = __expf(f0.y - mm.y);
    float e1x = __expf(f1.x - mm.x), e1y = __expf(f1.y - mm.y);
    red[j][wp] = make_float2(e0x + e1x, e0y + e1y);
    __syncthreads();
    float2 ss = make_float2(0.f, 0.f);
#pragma unroll
    for (int q = 0; q < 16; q++) {
        float2 r = red[q][wp];
        ss.x += r.x;
        ss.y += r.y;
    }
    float ix = 1.0f / ss.x, iy = 1.0f / ss.y;

    p[t] = packh(e0x * ix, e0y * iy);
    p[t + 256] = packh(e1x * ix, e1y * iy);
}

// ============================================================================
// Kernel 3: V GEMM (fp16 mma), R11 structure; sA is a pure uint4 copy.
// Per b: M=128 (d tile), N'=64 (all k), contraction n=1024 in chunks of 32.
// Epilogue: V = C - 32*c^T; warp-local L2 norm over k; write g_v[b][d][k].
// ============================================================================
#define VP 20
__global__ __launch_bounds__(256, 2) void k_vlad(const float* __restrict__ x,
                                                 const float* __restrict__ cc) {
    __shared__ uint32_t sA[64][VP];    // [k][n-pair 16] f16x2
    __shared__ uint32_t sX[128][VP];   // [d][n-pair 16] f16x2

    const int b = blockIdx.y, d0 = blockIdx.x * 128;
    const int t = threadIdx.x, lane = t & 31, warp = t >> 5;
    const int g = lane >> 2, tq = lane & 3;
    const int m0 = warp * 16;
    const float* xb = x + (size_t)b * DD * NN;
    const uint32_t* ab = g_a16u + (size_t)b * KK * (NN / 2);

    float acc[8][4];
#pragma unroll
    for (int j = 0; j < 8; j++)
#pragma unroll
        for (int r = 0; r < 4; r++) acc[j][r] = 0.f;

    const int arow = t & 63, aseg = t >> 6;   // a loader: 64 rows x 4 uint4
    const int xrow = t >> 1, xseg = t & 1;    // x loader: 128 rows x 2 x 16f

    for (int n0 = 0; n0 < NN; n0 += 32) {
        {
            uint4 ra = *(const uint4*)(ab + (size_t)arow * (NN / 2) + n0 / 2 + aseg * 4);
            *(uint4*)&sA[arow][aseg * 4] = ra;
        }
        {
            const float* src = xb + (size_t)(d0 + xrow) * NN + n0 + xseg * 16;
            float4 v0 = *(const float4*)src;
            float4 v1 = *(const float4*)(src + 4);
            float4 v2 = *(const float4*)(src + 8);
            float4 v3 = *(const float4*)(src + 12);
            *(uint4*)&sX[xrow][xseg * 8] =
                make_uint4(packh(v0.x, v0.y), packh(v0.z, v0.w),
                           packh(v1.x, v1.y), packh(v1.z, v1.w));
            *(uint4*)&sX[xrow][xseg * 8 + 4] =
                make_uint4(packh(v2.x, v2.y), packh(v2.z, v2.w),
                           packh(v3.x, v3.y), packh(v3.z, v3.w));
        }
        __syncthreads();

#pragma unroll
        for (int s = 0; s < 2; s++) {
            const int sp = s * 8;
            uint32_t a[4];
            a[0] = sX[m0 + g][sp + tq];
            a[1] = sX[m0 + g + 8][sp + tq];
            a[2] = sX[m0 + g][sp + tq + 4];
            a[3] = sX[m0 + g + 8][sp + tq + 4];
#pragma unroll
            for (int j = 0; j < 8; j++) {
                const int kc = j * 8 + g;
                uint32_t b0 = sA[kc][sp + tq];
                uint32_t b1 = sA[kc][sp + tq + 4];
                mma16(acc[j], a, b0, b1);
            }
        }
        __syncthreads();
    }

    // epilogue: rows d = d0+m0+g (+8); cols k = j*8+2tq(+1)
#pragma unroll
    for (int half = 0; half < 2; half++) {
        const int d = d0 + m0 + g + half * 8;
        float v[16];
        float s = 0.f;
#pragma unroll
        for (int j = 0; j < 8; j++) {
            const int k = j * 8 + 2 * tq;
            float c0 = cc[(size_t)k * DD + d];
            float c1 = cc[(size_t)(k + 1) * DD + d];
            float v0 = acc[j][half * 2 + 0] - 32.f * c0;
            float v1 = acc[j][half * 2 + 1] - 32.f * c1;
            v[j * 2] = v0; v[j * 2 + 1] = v1;
            s += v0 * v0 + v1 * v1;
        }
        s += __shfl_xor_sync(0xffffffffu, s, 1);
        s += __shfl_xor_sync(0xffffffffu, s, 2);
        float n1 = fmaxf(sqrtf(s), EPSN);
        float n2 = fmaxf(sqrtf(s) / n1, EPSN);
        float inv = 1.0f / (n1 * n2);
        float* dst = g_v + ((size_t)b * DD + d) * KK;
#pragma unroll
        for (int j = 0; j < 8; j++)
            *(float2*)(dst + j * 8 + 2 * tq) =
                make_float2(v[j * 2] * inv, v[j * 2 + 1] * inv);
    }
}

// ============================================================================
// Kernel 4: transpose g_v [b][dk] -> out [dk][b]
// ============================================================================
__global__ __launch_bounds__(256) void k_tr(float* __restrict__ out) {
    __shared__ float tile[32][33];
    const int bx = blockIdx.x * 32;   // dk
    const int by = blockIdx.y * 32;   // b
    const int tx = threadIdx.x & 31;
    const int ty = threadIdx.x >> 5;

#pragma unroll
    for (int i = 0; i < 32; i += 8)
        tile[ty + i][tx] = g_v[(size_t)(by + ty + i) * (DD * KK) + bx + tx];
    __syncthreads();
#pragma unroll
    for (int i = 0; i < 32; i += 8)
        out[(size_t)(bx + ty + i) * BB + by + tx] = tile[tx][ty + i];
}

// ============================================================================
extern "C" void kernel_launch(void* const* d_in, const int* in_sizes, int n_in,
                              void* d_out, int out_size) {
    const float* x  = (const float*)d_in[0];
    const float* wt = (const float*)d_in[1];
    const float* c  = (const float*)d_in[2];
    float* out = (float*)d_out;

    k_feat<<<dim3(NN / 256, BB), 256>>>(x, wt);

    k_softmax<<<BB * KK, 256>>>();

    k_vlad<<<dim3(DD / 128, BB), 256>>>(x, c);

    k_tr<<<dim3(DD * KK / 32, BB / 32), 256>>>(out);
}

// round 17
// speedup vs baseline: 1.1465x; 1.0487x over previous
#include <cuda_runtime.h>
#include <cuda_fp16.h>
#include <cstdint>

// NetVladCNN: B=64, D=512, H=W=32 (N=1024), K=64
// x: (B,D,H,W) fp32   w: (K,D)   c: (K,D)   out: (D,K,B) fp32
//
// Stage 1 (fp16 mma): features = w·x -> g_a16u; ALSO exports x as fp16 d-pair
//         packed u32 tiles to g_x16 (the loader computes them anyway).
// Stage 2: softmax over h on fp16 pairs (fp32 math)
// Stage 3 (fp16 mma): reads g_x16 (half the bytes, L2-warm); C[d,k]; V=C-32c^T;
//         warp-local k-normalize; g_v[b][d][k]
// Stage 4: transpose g_v [b][dk] -> out [dk][b]

#define BB 64
#define DD 512
#define NN 1024
#define KK 64
#define EPSN 1e-12f

__device__ uint32_t g_a16u[(size_t)BB * KK * (NN / 2)];   // fp16x2 features / a
__device__ uint32_t g_x16[(size_t)BB * (DD / 2) * NN];    // fp16x2 x, pair across d
__device__ float g_v[(size_t)BB * DD * KK];               // normalized V

// ---------- fp16 mma helpers ----------
__device__ __forceinline__ void mma16(float* c, const uint32_t* a, uint32_t b0,
                                      uint32_t b1) {
    asm volatile(
        "mma.sync.aligned.m16n8k16.row.col.f32.f16.f16.f32 "
        "{%0,%1,%2,%3}, {%4,%5,%6,%7}, {%8,%9}, {%0,%1,%2,%3};"
        : "+f"(c[0]), "+f"(c[1]), "+f"(c[2]), "+f"(c[3])
        : "r"(a[0]), "r"(a[1]), "r"(a[2]), "r"(a[3]), "r"(b0), "r"(b1));
}
__device__ __forceinline__ uint32_t packh(float e, float o) {
    uint32_t r;
    asm("cvt.rn.f16x2.f32 %0, %1, %2;" : "=r"(r) : "f"(o), "f"(e));
    return r;
}
__device__ __forceinline__ uint32_t prmt(uint32_t a, uint32_t b, uint32_t sel) {
    uint32_t r;
    asm("prmt.b32 %0, %1, %2, %3;" : "=r"(r) : "r"(a), "r"(b), "r"(sel));
    return r;
}

// ============================================================================
// Kernel 1: features GEMM (fp16 mma) + x16 export.
// Per b: M=64 (k), N'=256 (n tile), contraction d=512 in chunks of 32.
// 256 thr = 8 warps; warp tile = m32 x n64 (2 m-tiles x 8 n-frags).
// ============================================================================
#define WPAD 20
#define XPAD 264
__global__ __launch_bounds__(256, 2) void k_feat(const float* __restrict__ x,
                                                 const float* __restrict__ wt) {
    __shared__ uint32_t sW[64][WPAD];   // [k][d-pair 16] f16x2
    __shared__ uint32_t sX[16][XPAD];   // [d-pair][n 256] f16x2

    const int b = blockIdx.y, n0 = blockIdx.x * 256;
    const int t = threadIdx.x, lane = t & 31, warp = t >> 5;
    const int g = lane >> 2, tq = lane & 3;
    const int k0 = (warp >> 2) * 32;
    const int nb = (warp & 3) * 64;
    const float* xb = x + (size_t)b * DD * NN;
    uint32_t* x16b = g_x16 + (size_t)b * (DD / 2) * NN;

    float acc[2][8][4];
#pragma unroll
    for (int i = 0; i < 2; i++)
#pragma unroll
        for (int j = 0; j < 8; j++)
#pragma unroll
            for (int r = 0; r < 4; r++) acc[i][j][r] = 0.f;

    const int wrow = t & 63, wseg = t >> 6;   // w loader
    const int xdp = t >> 4, xtx = t & 15;     // x loader

    for (int d0 = 0; d0 < DD; d0 += 32) {
        {
            const float* src = wt + (size_t)wrow * DD + d0 + wseg * 8;
            float4 v0 = *(const float4*)src;
            float4 v1 = *(const float4*)(src + 4);
            sW[wrow][wseg * 4 + 0] = packh(v0.x, v0.y);
            sW[wrow][wseg * 4 + 1] = packh(v0.z, v0.w);
            sW[wrow][wseg * 4 + 2] = packh(v1.x, v1.y);
            sW[wrow][wseg * 4 + 3] = packh(v1.z, v1.w);
        }
        {
            const float* se = xb + (size_t)(d0 + 2 * xdp) * NN + n0;
            const float* so = se + NN;
            uint32_t* xdst = x16b + (size_t)((d0 >> 1) + xdp) * NN + n0;
#pragma unroll
            for (int q = 0; q < 4; q++) {
                const int col = xtx * 4 + 64 * q;
                float4 ve = *(const float4*)(se + col);
                float4 vo = *(const float4*)(so + col);
                uint4 pk = make_uint4(packh(ve.x, vo.x), packh(ve.y, vo.y),
                                      packh(ve.z, vo.z), packh(ve.w, vo.w));
                *(uint4*)&sX[xdp][col] = pk;
                *(uint4*)(xdst + col) = pk;   // export fp16 x (d-pair packed)
            }
        }
        __syncthreads();

#pragma unroll
        for (int s = 0; s < 2; s++) {
            const int sp = s * 8;
            uint32_t a[2][4];
#pragma unroll
            for (int mi = 0; mi < 2; mi++) {
                const int r0 = k0 + mi * 16 + g;
                a[mi][0] = sW[r0][sp + tq];
                a[mi][1] = sW[r0 + 8][sp + tq];
                a[mi][2] = sW[r0][sp + tq + 4];
                a[mi][3] = sW[r0 + 8][sp + tq + 4];
            }
#pragma unroll
            for (int j = 0; j < 8; j++) {
                const int n = nb + j * 8 + g;
                uint32_t b0 = sX[sp + tq][n];
                uint32_t b1 = sX[sp + tq + 4][n];
                mma16(acc[0][j], a[0], b0, b1);
                mma16(acc[1][j], a[1], b0, b1);
            }
        }
        __syncthreads();
    }

    // epilogue: pack fp16 pairs (n, n+1) into g_a16u
#pragma unroll
    for (int mi = 0; mi < 2; mi++) {
#pragma unroll
        for (int j = 0; j < 8; j++) {
            const int k = k0 + mi * 16 + g;
            const int np = (n0 + nb + j * 8 + 2 * tq) >> 1;
            g_a16u[((size_t)b * KK + k) * (NN / 2) + np] =
                packh(acc[mi][j][0], acc[mi][j][1]);
            g_a16u[((size_t)b * KK + k + 8) * (NN / 2) + np] =
                packh(acc[mi][j][2], acc[mi][j][3]);
        }
    }
}

// ============================================================================
// Kernel 2: softmax over h on fp16 pairs. One block per (b,k) row.
// ============================================================================
__global__ __launch_bounds__(256) void k_softmax() {
    __shared__ float2 red[16][17];
    uint32_t* p = g_a16u + (size_t)blockIdx.x * (NN / 2);
    const int t = threadIdx.x;
    const int j = t >> 4, wp = t & 15;

    uint32_t u0 = p[t], u1 = p[t + 256];   // h = j, h = j+16
    float2 f0 = __half22float2(*(__half2*)&u0);
    float2 f1 = __half22float2(*(__half2*)&u1);

    red[j][wp] = make_float2(fmaxf(f0.x, f1.x), fmaxf(f0.y, f1.y));
    __syncthreads();
    float2 mm = red[0][wp];
#pragma unroll
    for (int q = 1; q < 16; q++) {
        float2 r = red[q][wp];
        mm.x = fmaxf(mm.x, r.x);
        mm.y = fmaxf(mm.y, r.y);
    }
    __syncthreads();

    float e0x = __expf(f0.x - mm.x), e0y = __expf(f0.y - mm.y);
    float e1x = __expf(f1.x - mm.x), e1y = __expf(f1.y - mm.y);
    red[j][wp] = make_float2(e0x + e1x, e0y + e1y);
    __syncthreads();
    float2 ss = make_float2(0.f, 0.f);
#pragma unroll
    for (int q = 0; q < 16; q++) {
        float2 r = red[q][wp];
        ss.x += r.x;
        ss.y += r.y;
    }
    float ix = 1.0f / ss.x, iy = 1.0f / ss.y;

    p[t] = packh(e0x * ix, e0y * iy);
    p[t + 256] = packh(e1x * ix, e1y * iy);
}

// ============================================================================
// Kernel 3: V GEMM (fp16 mma), x from g_x16 (both parities consumed via prmt).
// Per b: M=128 (d tile), N'=64 (all k), contraction n=1024 in chunks of 32.
// Epilogue: V = C - 32*c^T; warp-local L2 norm over k; write g_v[b][d][k].
// ============================================================================
#define VP 20
__global__ __launch_bounds__(256, 2) void k_vlad(const float* __restrict__ cc) {
    __shared__ uint32_t sA[64][VP];    // [k][n-pair 16] f16x2
    __shared__ uint32_t sX[128][VP];   // [d][n-pair 16] f16x2

    const int b = blockIdx.y, d0 = blockIdx.x * 128;
    const int t = threadIdx.x, lane = t & 31, warp = t >> 5;
    const int g = lane >> 2, tq = lane & 3;
    const int m0 = warp * 16;
    const uint32_t* x16b = g_x16 + (size_t)b * (DD / 2) * NN;
    const uint32_t* ab = g_a16u + (size_t)b * KK * (NN / 2);

    float acc[8][4];
#pragma unroll
    for (int j = 0; j < 8; j++)
#pragma unroll
        for (int r = 0; r < 4; r++) acc[j][r] = 0.f;

    const int arow = t & 63, aseg = t >> 6;   // a loader: 64 rows x 4 uint4
    const int xdp = t >> 2, xsg = t & 3;      // x loader: 64 dp rows x 4 segs

    for (int n0 = 0; n0 < NN; n0 += 32) {
        {
            uint4 ra = *(const uint4*)(ab + (size_t)arow * (NN / 2) + n0 / 2 + aseg * 4);
            *(uint4*)&sA[arow][aseg * 4] = ra;
        }
        {
            // dp row holds (d=2dp, 2dp+1) per n; emit both parity rows.
            const uint32_t* src =
                x16b + (size_t)((d0 >> 1) + xdp) * NN + n0 + xsg * 8;
            uint4 u0 = *(const uint4*)src;
            uint4 u1 = *(const uint4*)(src + 4);
            *(uint4*)&sX[2 * xdp][xsg * 4] =
                make_uint4(prmt(u0.x, u0.y, 0x5410), prmt(u0.z, u0.w, 0x5410),
                           prmt(u1.x, u1.y, 0x5410), prmt(u1.z, u1.w, 0x5410));
            *(uint4*)&sX[2 * xdp + 1][xsg * 4] =
                make_uint4(prmt(u0.x, u0.y, 0x7632), prmt(u0.z, u0.w, 0x7632),
                           prmt(u1.x, u1.y, 0x7632), prmt(u1.z, u1.w, 0x7632));
        }
        __syncthreads();

#pragma unroll
        for (int s = 0; s < 2; s++) {
            const int sp = s * 8;
            uint32_t a[4];
            a[0] = sX[m0 + g][sp + tq];
            a[1] = sX[m0 + g + 8][sp + tq];
            a[2] = sX[m0 + g][sp + tq + 4];
            a[3] = sX[m0 + g + 8][sp + tq + 4];
#pragma unroll
            for (int j = 0; j < 8; j++) {
                const int kc = j * 8 + g;
                uint32_t b0 = sA[kc][sp + tq];
                uint32_t b1 = sA[kc][sp + tq + 4];
                mma16(acc[j], a, b0, b1);
            }
        }
        __syncthreads();
    }

    // epilogue: rows d = d0+m0+g (+8); cols k = j*8+2tq(+1)
#pragma unroll
    for (int half = 0; half < 2; half++) {
        const int d = d0 + m0 + g + half * 8;
        float v[16];
        float s = 0.f;
#pragma unroll
        for (int j = 0; j < 8; j++) {
            const int k = j * 8 + 2 * tq;
            float c0 = cc[(size_t)k * DD + d];
            float c1 = cc[(size_t)(k + 1) * DD + d];
            float v0 = acc[j][half * 2 + 0] - 32.f * c0;
            float v1 = acc[j][half * 2 + 1] - 32.f * c1;
            v[j * 2] = v0; v[j * 2 + 1] = v1;
            s += v0 * v0 + v1 * v1;
        }
        s += __shfl_xor_sync(0xffffffffu, s, 1);
        s += __shfl_xor_sync(0xffffffffu, s, 2);
        float n1 = fmaxf(sqrtf(s), EPSN);
        float n2 = fmaxf(sqrtf(s) / n1, EPSN);
        float inv = 1.0f / (n1 * n2);
        float* dst = g_v + ((size_t)b * DD + d) * KK;
#pragma unroll
        for (int j = 0; j < 8; j++)
            *(float2*)(dst + j * 8 + 2 * tq) =
                make_float2(v[j * 2] * inv, v[j * 2 + 1] * inv);
    }
}

// ============================================================================
// Kernel 4: transpose g_v [b][dk] -> out [dk][b]
// ============================================================================
__global__ __launch_bounds__(256) void k_tr(float* __restrict__ out) {
    __shared__ float tile[32][33];
    const int bx = blockIdx.x * 32;   // dk
    const int by = blockIdx.y * 32;   // b
    const int tx = threadIdx.x & 31;
    const int ty = threadIdx.x >> 5;

#pragma unroll
    for (int i = 0; i < 32; i += 8)
        tile[ty + i][tx] = g_v[(size_t)(by + ty + i) * (DD * KK) + bx + tx];
    __syncthreads();
#pragma unroll
    for (int i = 0; i < 32; i += 8)
        out[(size_t)(bx + ty + i) * BB + by + tx] = tile[tx][ty + i];
}

// ============================================================================
extern "C" void kernel_launch(void* const* d_in, const int* in_sizes, int n_in,
                              void* d_out, int out_size) {
    const float* x  = (const float*)d_in[0];
    const float* wt = (const float*)d_in[1];
    const float* c  = (const float*)d_in[2];
    float* out = (float*)d_out;

    k_feat<<<dim3(NN / 256, BB), 256>>>(x, wt);

    k_softmax<<<BB * KK, 256>>>();

    k_vlad<<<dim3(DD / 128, BB), 256>>>(c);

    k_tr<<<dim3(DD * KK / 32, BB / 32), 256>>>(out);
}